// round 17
// baseline (speedup 1.0000x reference)
#include <cuda_runtime.h>
#include <math.h>
#include <stdint.h>

#define B_TOTAL 16384

// ---------------- scratch (device globals; no allocation allowed) ----------
__device__ float g_h1[B_TOTAL * 6 * 14 * 14];   // after conv1+relu+pool
__device__ float g_h2[B_TOTAL * 400];           // after conv2+relu+pool (flat)
__device__ float g_h3[B_TOTAL * 120];           // after fc1+relu
__device__ float g_h4[B_TOTAL * 84];            // after fc2+relu

// pre-converted tf32 expert weights, PAIRWISE layout for float2 B-frag loads:
#define W1CH 5632
#define W2CH 6912
__device__ float g_w1t[64 * W1CH];
__device__ float g_w2t[64 * W2CH];

// ---------------------------------------------------------------------------
// helpers
// ---------------------------------------------------------------------------
__device__ __forceinline__ float to_tf32(float f) {
    uint32_t u;
    asm("cvt.rna.tf32.f32 %0, %1;" : "=r"(u) : "f"(f));
    return __uint_as_float(u);
}

__device__ __forceinline__ void mma_tf32(float c[4],
                                         uint32_t a0, uint32_t a1, uint32_t a2, uint32_t a3,
                                         uint32_t b0, uint32_t b1) {
    asm volatile(
        "mma.sync.aligned.m16n8k8.row.col.f32.tf32.tf32.f32 "
        "{%0,%1,%2,%3}, {%4,%5,%6,%7}, {%8,%9}, {%0,%1,%2,%3};\n"
        : "+f"(c[0]), "+f"(c[1]), "+f"(c[2]), "+f"(c[3])
        : "r"(a0), "r"(a1), "r"(a2), "r"(a3), "r"(b0), "r"(b1));
}

#define CP16(dst, src) \
    asm volatile("cp.async.cg.shared.global [%0], [%1], 16;\n" \
                 :: "r"(dst), "l"(src))

// ---------------------------------------------------------------------------
// weight pre-pass kernels (pairwise repack + tf32 convert)
// ---------------------------------------------------------------------------
__global__ __launch_bounds__(256) void prep_w1(const float* __restrict__ w1)
{
    int idx = blockIdx.x * 256 + threadIdx.x;
    if (idx >= 64 * W1CH) return;
    int cc = idx / W1CH;
    int r  = idx % W1CH;
    int n  = r / 88;
    int q  = r % 88;
    int ks = q >> 3;
    int tig = (q & 7) >> 1;
    int h  = q & 1;
    int k  = ks * 8 + tig + h * 4;
    int e  = cc >> 5, c = cc & 31;
    float v = 0.f;
    if (k < 84) v = to_tf32(w1[((size_t)e * 84 + k) * 2048 + c * 64 + n]);
    g_w1t[idx] = v;
}

__global__ __launch_bounds__(256) void prep_w2(const float* __restrict__ w2)
{
    int idx = blockIdx.x * 256 + threadIdx.x;
    if (idx >= 64 * W2CH) return;
    int cc = idx / W2CH;
    int r  = idx % W2CH;
    int d  = r / 72;
    int q  = r % 72;
    float v = 0.f;
    if (q < 64) {
        int hb  = q >> 3;
        int tig = (q & 7) >> 1;
        int h   = q & 1;
        int kk  = hb * 8 + tig + h * 4;
        int e   = cc >> 5, c = cc & 31;
        if (d < 84) v = to_tf32(w2[((size_t)e * 2048 + c * 64 + kk) * 84 + d]);
    }
    g_w2t[idx] = v;
}

// ---------------------------------------------------------------------------
// conv1 (tensor core): x[B,3,32,32] -> relu(maxpool2(conv5x5,6ch)) -> [B,6,14,14]
// Implicit-im2col tf32 mma. (R14 winner, unchanged)
// ---------------------------------------------------------------------------
#define C1_IMG   3072
#define C1_CONV  (784 * 9)
#define C1_OFF_IMG   0
#define C1_OFF_WB    (2 * C1_IMG)
#define C1_OFF_CONV  (C1_OFF_WB + 640)
#define C1_OFF_B     (C1_OFF_CONV + 2 * C1_CONV)
#define C1_SMEM_FLOATS (C1_OFF_B + 8)

__global__ __launch_bounds__(256) void conv1_kernel(
    const float* __restrict__ x, const float* __restrict__ w,
    const float* __restrict__ b, float* __restrict__ out)
{
    extern __shared__ float c1sm[];
    float*  s_img  = c1sm + C1_OFF_IMG;
    float2* s_wB   = (float2*)(c1sm + C1_OFF_WB);
    float*  s_conv = c1sm + C1_OFF_CONV;
    float*  s_b    = c1sm + C1_OFF_B;

    const int img0 = blockIdx.x * 2;
    const int tid  = threadIdx.x;
    const int lane = tid & 31, wid = tid >> 5;
    const int gid  = lane >> 2, tig = lane & 3;

    for (int i = tid; i < 320; i += 256) {
        int ks = i >> 5, l = i & 31;
        int g = l >> 2, t = l & 3;
        int k0 = ks * 8 + t, k1 = k0 + 4;
        float w0 = (k0 < 75 && g < 6) ? w[g * 75 + k0] : 0.f;
        float w1 = (k1 < 75 && g < 6) ? w[g * 75 + k1] : 0.f;
        s_wB[i] = make_float2(to_tf32(w0), to_tf32(w1));
    }
    if (tid < 8) s_b[tid] = (tid < 6) ? b[tid] : 0.f;
    for (int i = tid; i < 2 * C1_IMG; i += 256)
        s_img[i] = to_tf32(x[(size_t)img0 * C1_IMG + i]);
    __syncthreads();

    uint32_t B0[10], B1[10];
#pragma unroll
    for (int ks = 0; ks < 10; ks++) {
        float2 p = s_wB[ks * 32 + lane];
        B0[ks] = __float_as_uint(p.x);
        B1[ks] = __float_as_uint(p.y);
    }
    int off0[10], off4[10];
#pragma unroll
    for (int ks = 0; ks < 10; ks++) {
        int k = ks * 8 + tig;
        int kk = (k < 75) ? k : 0;
        off0[ks] = (kk / 25) * 1024 + ((kk % 25) / 5) * 32 + (kk % 5);
        k += 4; kk = (k < 75) ? k : 0;
        off4[ks] = (kk / 25) * 1024 + ((kk % 25) / 5) * 32 + (kk % 5);
    }

    for (int t = wid; t < 98; t += 8) {
        int img  = t / 49, tile = t % 49;
        int m_lo = tile * 16 + gid;
        int m_hi = m_lo + 8;
        const float* ib = s_img + img * C1_IMG;
        int p_lo = (m_lo / 28) * 32 + (m_lo % 28);
        int p_hi = (m_hi / 28) * 32 + (m_hi % 28);
        float c[4] = {0.f, 0.f, 0.f, 0.f};
#pragma unroll
        for (int ks = 0; ks < 10; ks++) {
            uint32_t a0 = __float_as_uint(ib[p_lo + off0[ks]]);
            uint32_t a1 = __float_as_uint(ib[p_hi + off0[ks]]);
            uint32_t a2 = __float_as_uint(ib[p_lo + off4[ks]]);
            uint32_t a3 = __float_as_uint(ib[p_hi + off4[ks]]);
            mma_tf32(c, a0, a1, a2, a3, B0[ks], B1[ks]);
        }
        float* sc = s_conv + img * C1_CONV;
        sc[m_lo * 9 + 2 * tig    ] = c[0];
        sc[m_lo * 9 + 2 * tig + 1] = c[1];
        sc[m_hi * 9 + 2 * tig    ] = c[2];
        sc[m_hi * 9 + 2 * tig + 1] = c[3];
    }
    __syncthreads();

    for (int o = tid; o < 2352; o += 256) {
        int img = o / 1176;
        int r   = o % 1176;
        int oc  = r / 196;
        int pp  = r % 196;
        int py = pp / 14, px = pp % 14;
        const float* sc = s_conv + img * C1_CONV;
        int q0 = (2 * py) * 28 + 2 * px;
        float v = fmaxf(fmaxf(sc[ q0       * 9 + oc], sc[(q0 +  1) * 9 + oc]),
                        fmaxf(sc[(q0 + 28) * 9 + oc], sc[(q0 + 29) * 9 + oc]));
        out[(size_t)(img0 + img) * 1176 + oc * 196 + pp] = fmaxf(v + s_b[oc], 0.f);
    }
}

// ---------------------------------------------------------------------------
// conv2 (tensor core): h1[B,6,14,14] -> relu(maxpool2(conv5x5,16ch)) -> [B,400]
// Implicit-im2col tf32 mma. FIXED: weight-fragment region is 2432 floats
// (1216 float2), previously under-sized at 1216 floats -> aliased s_conv.
// ---------------------------------------------------------------------------
#define C2_NIMG  4
#define C2_IN    1176
#define C2_CONV  (112 * 17)
#define C2_OFF_IN   0
#define C2_OFF_WB   (C2_NIMG * C2_IN)                 // 4704
#define C2_OFF_CONV (C2_OFF_WB + 2432)                // 7136 (2*19*32 float2)
#define C2_OFF_B    (C2_OFF_CONV + C2_NIMG * C2_CONV) // 14752
#define C2_SMEM_FLOATS (C2_OFF_B + 16)                // 14768 (59.1 KB)

__global__ __launch_bounds__(256) void conv2_kernel(
    const float* __restrict__ in, const float* __restrict__ w,
    const float* __restrict__ b, float* __restrict__ out)
{
    extern __shared__ float c2sm[];
    float*  s_in   = c2sm + C2_OFF_IN;
    float2* s_wB   = (float2*)(c2sm + C2_OFF_WB);   // [2 nb][19 ks][32 lane]
    float*  s_conv = c2sm + C2_OFF_CONV;
    float*  s_b    = c2sm + C2_OFF_B;

    const int img0 = blockIdx.x * C2_NIMG;
    const int tid  = threadIdx.x;
    const int lane = tid & 31, wid = tid >> 5;
    const int gid  = lane >> 2, tig = lane & 3;

    // weight fragments
    for (int i = tid; i < 2 * 19 * 32; i += 256) {
        int l  = i & 31;
        int r  = i >> 5;            // 0..37
        int nb = r / 19, ks = r % 19;
        int g = l >> 2, t = l & 3;
        int n = nb * 8 + g;
        int k0 = ks * 8 + t, k1 = k0 + 4;
        float w0 = (k0 < 150) ? w[n * 150 + k0] : 0.f;
        float w1 = (k1 < 150) ? w[n * 150 + k1] : 0.f;
        s_wB[i] = make_float2(to_tf32(w0), to_tf32(w1));
    }
    if (tid < 16) s_b[tid] = b[tid];
    for (int i = tid; i < C2_NIMG * C2_IN; i += 256)
        s_in[i] = to_tf32(in[(size_t)img0 * C2_IN + i]);
    __syncthreads();

    // per-thread K offsets: k -> ic*196 + ky*14 + kx (pad k -> 0, W=0)
    int off0[19], off4[19];
#pragma unroll
    for (int ks = 0; ks < 19; ks++) {
        int k = ks * 8 + tig;
        int kk = (k < 150) ? k : 0;
        off0[ks] = (kk / 25) * 196 + ((kk % 25) / 5) * 14 + (kk % 5);
        k += 4; kk = (k < 150) ? k : 0;
        off4[ks] = (kk / 25) * 196 + ((kk % 25) / 5) * 14 + (kk % 5);
    }

    // mma tiles: 4 img x 7 tiles
    for (int t = wid; t < C2_NIMG * 7; t += 8) {
        int img = t / 7, tile = t % 7;
        int m_lo = tile * 16 + gid;
        int m_hi = m_lo + 8;
        int pl = (m_lo < 100) ? m_lo : 99;   // clamp pad rows (discarded later)
        int ph = (m_hi < 100) ? m_hi : 99;
        int base_lo = (pl / 10) * 14 + (pl % 10);
        int base_hi = (ph / 10) * 14 + (ph % 10);
        const float* ib = s_in + img * C2_IN;
        float c0[4] = {0.f, 0.f, 0.f, 0.f};
        float c1[4] = {0.f, 0.f, 0.f, 0.f};
#pragma unroll
        for (int ks = 0; ks < 19; ks++) {
            uint32_t a0 = __float_as_uint(ib[base_lo + off0[ks]]);
            uint32_t a1 = __float_as_uint(ib[base_hi + off0[ks]]);
            uint32_t a2 = __float_as_uint(ib[base_lo + off4[ks]]);
            uint32_t a3 = __float_as_uint(ib[base_hi + off4[ks]]);
            float2 b0 = s_wB[ks * 32 + lane];
            float2 b1 = s_wB[(19 + ks) * 32 + lane];
            mma_tf32(c0, a0, a1, a2, a3, __float_as_uint(b0.x), __float_as_uint(b0.y));
            mma_tf32(c1, a0, a1, a2, a3, __float_as_uint(b1.x), __float_as_uint(b1.y));
        }
        float* sc = s_conv + img * C2_CONV;
        sc[m_lo * 17 +     2 * tig    ] = c0[0];
        sc[m_lo * 17 +     2 * tig + 1] = c0[1];
        sc[m_hi * 17 +     2 * tig    ] = c0[2];
        sc[m_hi * 17 +     2 * tig + 1] = c0[3];
        sc[m_lo * 17 + 8 + 2 * tig    ] = c1[0];
        sc[m_lo * 17 + 8 + 2 * tig + 1] = c1[1];
        sc[m_hi * 17 + 8 + 2 * tig    ] = c1[2];
        sc[m_hi * 17 + 8 + 2 * tig + 1] = c1[3];
    }
    __syncthreads();

    // pooling: 4 img x 16 oc x 5x5
    for (int o = tid; o < C2_NIMG * 400; o += 256) {
        int img = o / 400;
        int r   = o % 400;
        int oc  = r / 25;
        int pp  = r % 25;
        int py = pp / 5, px = pp % 5;
        const float* sc = s_conv + img * C2_CONV;
        int q = (2 * py) * 10 + 2 * px;
        float v = fmaxf(fmaxf(sc[ q       * 17 + oc], sc[(q +  1) * 17 + oc]),
                        fmaxf(sc[(q + 10) * 17 + oc], sc[(q + 11) * 17 + oc]));
        out[(size_t)(img0 + img) * 400 + r] = fmaxf(v + s_b[oc], 0.f);
    }
}

// ---------------------------------------------------------------------------
// Generic tiled GEMM: C[M,N] = act(A[M,K] @ W[K,N] + bias), 64x64x16 tiles.
// ---------------------------------------------------------------------------
__global__ __launch_bounds__(256) void gemm_bias_relu(
    const float* __restrict__ A, const float* __restrict__ W,
    const float* __restrict__ bias, float* __restrict__ C,
    int M, int N, int K, int doRelu)
{
    __shared__ float As[16][65];
    __shared__ float Ws[16][64];

    int n0 = blockIdx.x * 64;
    int m0 = blockIdx.y * 64;
    int tx = threadIdx.x & 15;
    int ty = threadIdx.x >> 4;

    float acc[4][4];
#pragma unroll
    for (int i = 0; i < 4; i++)
#pragma unroll
        for (int j = 0; j < 4; j++) acc[i][j] = 0.f;

    for (int k0 = 0; k0 < K; k0 += 16) {
#pragma unroll
        for (int q = 0; q < 4; q++) {
            int idx = threadIdx.x + q * 256;
            int m = idx >> 4, kk = idx & 15;
            int gk = k0 + kk;
            As[kk][m] = (gk < K) ? A[(size_t)(m0 + m) * K + gk] : 0.f;
        }
#pragma unroll
        for (int q = 0; q < 4; q++) {
            int idx = threadIdx.x + q * 256;
            int kk = idx >> 6, n = idx & 63;
            int gk = k0 + kk, gn = n0 + n;
            Ws[kk][n] = (gk < K && gn < N) ? W[(size_t)gk * N + gn] : 0.f;
        }
        __syncthreads();
#pragma unroll
        for (int kk = 0; kk < 16; kk++) {
            float a[4], bb[4];
#pragma unroll
            for (int i = 0; i < 4; i++) a[i] = As[kk][ty + 16 * i];
#pragma unroll
            for (int j = 0; j < 4; j++) bb[j] = Ws[kk][tx + 16 * j];
#pragma unroll
            for (int i = 0; i < 4; i++)
#pragma unroll
                for (int j = 0; j < 4; j++) acc[i][j] += a[i] * bb[j];
        }
        __syncthreads();
    }

#pragma unroll
    for (int i = 0; i < 4; i++) {
        int m = m0 + ty + 16 * i;
#pragma unroll
        for (int j = 0; j < 4; j++) {
            int n = n0 + tx + 16 * j;
            if (n < N && m < M) {
                float v = acc[i][j] + bias[n];
                if (doRelu) v = fmaxf(v, 0.f);
                C[(size_t)m * N + n] = v;
            }
        }
    }
}

// ---------------------------------------------------------------------------
// Fused MoE + fc3, tf32 mma. 128 tokens/block, 256 threads (8 warps).
// (exact R11/R13 version — best measured)
// ---------------------------------------------------------------------------
#define XS_STRIDE 92
#define OFF_X    0
#define OFF_W1   (128 * XS_STRIDE)
#define OFF_W2   (OFF_W1 + 2 * W1CH)
#define OFF_B1   (OFF_W2 + 2 * W2CH)
#define OFF_GW   (OFF_B1 + 128)
#define OFF_C    (OFF_GW + 168)
#define OFF_B2   (OFF_C + 256)
#define OFF_W3   (OFF_B2 + 168)
#define OFF_B3   (OFF_W3 + 840)
#define MOE_SMEM_FLOATS (OFF_B3 + 16)

__global__ __launch_bounds__(256) void moe_fc3_kernel(
    const float* __restrict__ x,
    const float* __restrict__ gate_w,
    const float* __restrict__ b1g,
    const float* __restrict__ b2,
    const float* __restrict__ w3,
    const float* __restrict__ b3,
    float* __restrict__ out)
{
    extern __shared__ float sm[];
    float* X_s  = sm + OFF_X;
    float* W1_s = sm + OFF_W1;
    float* W2_s = sm + OFF_W2;
    float* sb1  = sm + OFF_B1;
    float* sgw  = sm + OFF_GW;
    float* c_s  = sm + OFF_C;
    float* sb2  = sm + OFF_B2;
    float* sw3  = sm + OFF_W3;
    float* sb3  = sm + OFF_B3;

    const int tid = threadIdx.x;
    const int t0  = blockIdx.x * 128;

    const uint32_t smbase = (uint32_t)__cvta_generic_to_shared(sm);
    const uint32_t w1_sm  = smbase + OFF_W1 * 4;
    const uint32_t w2_sm  = smbase + OFF_W2 * 4;
    const uint32_t b1_sm  = smbase + OFF_B1 * 4;

    {
        const float4* s1 = (const float4*)(g_w1t);
        for (int i = tid; i < W1CH / 4; i += 256) CP16(w1_sm + i * 16, s1 + i);
        const float4* s2 = (const float4*)(g_w2t);
        for (int i = tid; i < W2CH / 4; i += 256) CP16(w2_sm + i * 16, s2 + i);
        if (tid < 16) CP16(b1_sm + tid * 16, (const float4*)b1g + tid);
    }
    asm volatile("cp.async.commit_group;\n" ::: "memory");

    for (int i = tid; i < 128 * 84; i += 256) {
        int t = i / 84, k = i % 84;
        X_s[t * XS_STRIDE + k] = x[(size_t)(t0 + t) * 84 + k];
    }
    for (int i = tid; i < 128 * 8; i += 256) {
        int t = i / 8, k = 84 + (i % 8);
        X_s[t * XS_STRIDE + k] = 0.f;
    }
    for (int i = tid; i < 168; i += 256) sgw[i] = gate_w[i];
    for (int i = tid; i < 168; i += 256) sb2[i] = b2[i];
    for (int i = tid; i < 840; i += 256) sw3[i] = w3[i];
    if (tid < 10) sb3[tid] = b3[tid];
    __syncthreads();

    if (tid < 128) {
        float l0 = 0.f, l1 = 0.f;
        const float* xr = X_s + tid * XS_STRIDE;
#pragma unroll 4
        for (int k = 0; k < 84; k++) {
            l0 += xr[k] * sgw[k * 2 + 0];
            l1 += xr[k] * sgw[k * 2 + 1];
        }
        float m = fmaxf(l0, l1);
        float e0 = expf(l0 - m), e1 = expf(l1 - m);
        float inv = 1.f / (e0 + e1);
        c_s[tid * 2 + 0] = e0 * inv;
        c_s[tid * 2 + 1] = e1 * inv;
    }
    __syncthreads();

    for (int i = tid; i < 128 * XS_STRIDE; i += 256) X_s[i] = to_tf32(X_s[i]);
    __syncthreads();

    const int lane = tid & 31, wid = tid >> 5;
    const int gid = lane >> 2, tig = lane & 3;
    const int wm  = wid * 16;
    const int L0  = (lane & 0x1C) + (tig >> 1);
    const int L2  = L0 + 2;
    const bool odd = (tig & 1);

    const float gA0 = c_s[(wm + gid    ) * 2 + 0];
    const float gA1 = c_s[(wm + gid    ) * 2 + 1];
    const float gB0 = c_s[(wm + gid + 8) * 2 + 0];
    const float gB1 = c_s[(wm + gid + 8) * 2 + 1];

    uint32_t XA[11][4];
#pragma unroll
    for (int ks = 0; ks < 11; ks++) {
        int k = ks * 8 + tig;
        XA[ks][0] = __float_as_uint(X_s[(wm + gid    ) * XS_STRIDE + k    ]);
        XA[ks][1] = __float_as_uint(X_s[(wm + gid + 8) * XS_STRIDE + k    ]);
        XA[ks][2] = __float_as_uint(X_s[(wm + gid    ) * XS_STRIDE + k + 4]);
        XA[ks][3] = __float_as_uint(X_s[(wm + gid + 8) * XS_STRIDE + k + 4]);
    }

    float accY[12][4];
#pragma unroll
    for (int nb = 0; nb < 12; nb++)
#pragma unroll
        for (int r = 0; r < 4; r++) accY[nb][r] = 0.f;

    for (int cc = 0; cc < 64; cc++) {
        const int buf = cc & 1;
        const int e   = cc >> 5;

        asm volatile("cp.async.wait_group 0;\n" ::: "memory");
        __syncthreads();

        if (cc + 1 < 64) {
            const int nb2 = buf ^ 1;
            const float4* s1 = (const float4*)(g_w1t + (size_t)(cc + 1) * W1CH);
            uint32_t d1 = w1_sm + nb2 * (W1CH * 4);
            for (int i = tid; i < W1CH / 4; i += 256) CP16(d1 + i * 16, s1 + i);
            const float4* s2 = (const float4*)(g_w2t + (size_t)(cc + 1) * W2CH);
            uint32_t d2 = w2_sm + nb2 * (W2CH * 4);
            for (int i = tid; i < W2CH / 4; i += 256) CP16(d2 + i * 16, s2 + i);
            if (tid < 16)
                CP16(b1_sm + nb2 * 256 + tid * 16,
                     (const float4*)(b1g + (size_t)(cc + 1) * 64) + tid);
        }
        asm volatile("cp.async.commit_group;\n" ::: "memory");

        const float2* W1b = (const float2*)(W1_s + buf * W1CH);
        const float2* W2b = (const float2*)(W2_s + buf * W2CH);
        const float* b1b = sb1 + buf * 64;

        const float gl = e ? gA1 : gA0;
        const float gh = e ? gB1 : gB0;

        float accA[8][4];
#pragma unroll
        for (int nb = 0; nb < 8; nb++)
#pragma unroll
            for (int r = 0; r < 4; r++) accA[nb][r] = 0.f;

#pragma unroll
        for (int ks = 0; ks < 11; ks++) {
#pragma unroll
            for (int nb = 0; nb < 8; nb++) {
                int n = nb * 8 + gid;
                float2 bp = W1b[n * 44 + ks * 4 + tig];
                mma_tf32(accA[nb], XA[ks][0], XA[ks][1], XA[ks][2], XA[ks][3],
                         __float_as_uint(bp.x), __float_as_uint(bp.y));
            }
        }

#pragma unroll
        for (int hb = 0; hb < 8; hb++) {
            int n0 = hb * 8 + 2 * tig;
            float ba = b1b[n0], bbv = b1b[n0 + 1];
            float h0 = to_tf32(fmaxf(accA[hb][0] + ba , 0.f) * gl);
            float h1 = to_tf32(fmaxf(accA[hb][1] + bbv, 0.f) * gl);
            float h2 = to_tf32(fmaxf(accA[hb][2] + ba , 0.f) * gh);
            float h3 = to_tf32(fmaxf(accA[hb][3] + bbv, 0.f) * gh);

            float u0 = __shfl_sync(0xFFFFFFFFu, h0, L0);
            float u1 = __shfl_sync(0xFFFFFFFFu, h1, L0);
            float u2 = __shfl_sync(0xFFFFFFFFu, h2, L0);
            float u3 = __shfl_sync(0xFFFFFFFFu, h3, L0);
            float v0 = __shfl_sync(0xFFFFFFFFu, h0, L2);
            float v1 = __shfl_sync(0xFFFFFFFFu, h1, L2);
            float v2 = __shfl_sync(0xFFFFFFFFu, h2, L2);
            float v3 = __shfl_sync(0xFFFFFFFFu, h3, L2);
            uint32_t a0 = __float_as_uint(odd ? u1 : u0);
            uint32_t a1 = __float_as_uint(odd ? u3 : u2);
            uint32_t a2 = __float_as_uint(odd ? v1 : v0);
            uint32_t a3 = __float_as_uint(odd ? v3 : v2);

#pragma unroll
            for (int nb = 0; nb < 12; nb++) {
                int n = nb * 8 + gid;
                float2 bp = W2b[n * 36 + hb * 4 + tig];
                mma_tf32(accY[nb], a0, a1, a2, a3,
                         __float_as_uint(bp.x), __float_as_uint(bp.y));
            }
        }
    }

    __syncthreads();
    float* Y_s = W1_s;
    {
#pragma unroll
        for (int nb = 0; nb < 12; nb++) {
            int d = nb * 8 + 2 * tig;
            if (d < 84) {
                float bc = gA0 * sb2[d] + gA1 * sb2[84 + d];
                float bh = gB0 * sb2[d] + gB1 * sb2[84 + d];
                Y_s[(wm + gid    ) * 84 + d] = accY[nb][0] + bc;
                Y_s[(wm + gid + 8) * 84 + d] = accY[nb][2] + bh;
            }
            if (d + 1 < 84) {
                float bc = gA0 * sb2[d + 1] + gA1 * sb2[84 + d + 1];
                float bh = gB0 * sb2[d + 1] + gB1 * sb2[84 + d + 1];
                Y_s[(wm + gid    ) * 84 + d + 1] = accY[nb][1] + bc;
                Y_s[(wm + gid + 8) * 84 + d + 1] = accY[nb][3] + bh;
            }
        }
    }
    __syncthreads();

    for (int o = tid; o < 1280; o += 256) {
        int t = o / 10, cc = o % 10;
        float s = sb3[cc];
        const float* yr = Y_s + t * 84;
#pragma unroll 4
        for (int d = 0; d < 84; d++) s += yr[d] * sw3[d * 10 + cc];
        out[(size_t)(t0 + t) * 10 + cc] = s;
    }
}

// ---------------------------------------------------------------------------
extern "C" void kernel_launch(void* const* d_in, const int* in_sizes, int n_in,
                              void* d_out, int out_size)
{
    const float* x       = (const float*)d_in[0];
    const float* conv1_w = (const float*)d_in[1];
    const float* conv1_b = (const float*)d_in[2];
    const float* conv2_w = (const float*)d_in[3];
    const float* conv2_b = (const float*)d_in[4];
    const float* fc1_w   = (const float*)d_in[5];
    const float* fc1_b   = (const float*)d_in[6];
    const float* fc2_w   = (const float*)d_in[7];
    const float* fc2_b   = (const float*)d_in[8];
    const float* gate_w  = (const float*)d_in[9];
    const float* exp_w1  = (const float*)d_in[10];
    const float* exp_b1  = (const float*)d_in[11];
    const float* exp_w2  = (const float*)d_in[12];
    const float* exp_b2  = (const float*)d_in[13];
    const float* fc3_w   = (const float*)d_in[14];
    const float* fc3_b   = (const float*)d_in[15];
    float* out = (float*)d_out;

    const int B = B_TOTAL;

    float *h1, *h2, *h3, *h4;
    cudaGetSymbolAddress((void**)&h1, g_h1);
    cudaGetSymbolAddress((void**)&h2, g_h2);
    cudaGetSymbolAddress((void**)&h3, g_h3);
    cudaGetSymbolAddress((void**)&h4, g_h4);

    cudaFuncSetAttribute(moe_fc3_kernel,
                         cudaFuncAttributeMaxDynamicSharedMemorySize,
                         MOE_SMEM_FLOATS * (int)sizeof(float));
    cudaFuncSetAttribute(conv1_kernel,
                         cudaFuncAttributeMaxDynamicSharedMemorySize,
                         C1_SMEM_FLOATS * (int)sizeof(float));
    cudaFuncSetAttribute(conv2_kernel,
                         cudaFuncAttributeMaxDynamicSharedMemorySize,
                         C2_SMEM_FLOATS * (int)sizeof(float));

    // weight pre-pass (independent of conv path)
    prep_w1<<<(64 * W1CH + 255) / 256, 256>>>(exp_w1);
    prep_w2<<<(64 * W2CH + 255) / 256, 256>>>(exp_w2);

    conv1_kernel<<<B / 2, 256, C1_SMEM_FLOATS * (int)sizeof(float)>>>(
        x, conv1_w, conv1_b, h1);
    conv2_kernel<<<B / C2_NIMG, 256, C2_SMEM_FLOATS * (int)sizeof(float)>>>(
        h1, conv2_w, conv2_b, h2);

    dim3 g1(2, B / 64);
    gemm_bias_relu<<<g1, 256>>>(h2, fc1_w, fc1_b, h3, B, 120, 400, 1);
    dim3 g2(2, B / 64);
    gemm_bias_relu<<<g2, 256>>>(h3, fc2_w, fc2_b, h4, B, 84, 120, 1);

    moe_fc3_kernel<<<B / 128, 256, MOE_SMEM_FLOATS * (int)sizeof(float)>>>(
        h4, gate_w, exp_b1, exp_b2, fc3_w, fc3_b, out);
}